// round 15
// baseline (speedup 1.0000x reference)
#include <cuda_runtime.h>
#include <cuda_fp16.h>
#include <cstdint>

// Problem constants
#define NN 4096
#define FF 128
#define HID 128
#define HEADS 8
#define HDIM 16
#define CC 64
#define EE 131072

// ---------------- scratch (no allocation allowed) ----------------
__device__ float g_H[NN * HID];     // GEMM output of X@W (pre-gather)
__device__ float g_G[NN * HID];     // conv1 output (post-relu)
__device__ float g_G2[NN * HID];    // conv2 output (post-relu)
__device__ float g_QKV[NN * 3 * FF];
__device__ float g_O[NN * FF];      // attention output
__device__ float g_GNN[NN * CC];    // gnn branch output
__device__ float g_Wp[FF * CC];     // fused out_proj*proj weight
__device__ float g_bp[CC];          // fused bias
__device__ float g_dinv[NN];
__device__ int   g_count[NN];       // invariant: all-zero at kernel-launch entry
__device__ int   g_off[NN + 1];
__device__ int   g_cur[NN];
__device__ int   g_srow[EE];

// ---------------- helpers ----------------
__device__ __forceinline__ unsigned f16x2_hl(float hi, float lo) {
    unsigned u; asm("cvt.rn.f16x2.f32 %0, %1, %2;" : "=r"(u) : "f"(hi), "f"(lo)); return u;
}
__device__ __forceinline__ float ex2(float x) {
    float y; asm("ex2.approx.ftz.f32 %0, %1;" : "=f"(y) : "f"(x)); return y;
}
__device__ __forceinline__ void mma_f16(float c[4], unsigned a0, unsigned a1,
                                        unsigned a2, unsigned a3,
                                        unsigned b0, unsigned b1) {
    asm("mma.sync.aligned.m16n8k16.row.col.f32.f16.f16.f32 "
        "{%0,%1,%2,%3}, {%4,%5,%6,%7}, {%8,%9}, {%0,%1,%2,%3};"
        : "+f"(c[0]), "+f"(c[1]), "+f"(c[2]), "+f"(c[3])
        : "r"(a0), "r"(a1), "r"(a2), "r"(a3), "r"(b0), "r"(b1));
}

// ---------------- CSR build kernels ----------------
// hist: 4 edges per thread via int4 (g_count must be all-zero on entry;
// scan_kernel restores that invariant each launch)
__global__ void hist_kernel(const int* __restrict__ col, int* __restrict__ count) {
    int i = blockIdx.x * blockDim.x + threadIdx.x;
    if (i >= EE / 4) return;
    int4 v = ((const int4*)col)[i];
    atomicAdd(&count[v.x], 1);
    atomicAdd(&count[v.y], 1);
    atomicAdd(&count[v.z], 1);
    atomicAdd(&count[v.w], 1);
}

__global__ __launch_bounds__(1024)
void scan_kernel(int* __restrict__ count, int* __restrict__ off,
                 int* __restrict__ cur, float* __restrict__ dinv) {
    __shared__ int wsum[32];
    int t = threadIdx.x;
    int lane = t & 31, warp = t >> 5;
    int base = t * 4;
    int v0 = count[base + 0], v1 = count[base + 1];
    int v2 = count[base + 2], v3 = count[base + 3];
    // restore the all-zero invariant for the next launch
    count[base + 0] = 0; count[base + 1] = 0;
    count[base + 2] = 0; count[base + 3] = 0;
    dinv[base + 0] = rsqrtf(1.0f + (float)v0);
    dinv[base + 1] = rsqrtf(1.0f + (float)v1);
    dinv[base + 2] = rsqrtf(1.0f + (float)v2);
    dinv[base + 3] = rsqrtf(1.0f + (float)v3);
    int s = v0 + v1 + v2 + v3;
    int x = s;
    #pragma unroll
    for (int d = 1; d < 32; d <<= 1) {
        int y = __shfl_up_sync(0xffffffffu, x, d);
        if (lane >= d) x += y;
    }
    if (lane == 31) wsum[warp] = x;
    __syncthreads();
    if (warp == 0) {
        int w = wsum[lane];
        #pragma unroll
        for (int d = 1; d < 32; d <<= 1) {
            int y = __shfl_up_sync(0xffffffffu, w, d);
            if (lane >= d) w += y;
        }
        wsum[lane] = w;
    }
    __syncthreads();
    int run = x - s + (warp ? wsum[warp - 1] : 0);
    off[base + 0] = run; cur[base + 0] = run; run += v0;
    off[base + 1] = run; cur[base + 1] = run; run += v1;
    off[base + 2] = run; cur[base + 2] = run; run += v2;
    off[base + 3] = run; cur[base + 3] = run; run += v3;
    if (t == 1023) off[NN] = run;
}

__global__ void reorder_kernel(const int* __restrict__ row, const int* __restrict__ col,
                               int* __restrict__ cur, int* __restrict__ srow) {
    int e = blockIdx.x * blockDim.x + threadIdx.x;
    if (e >= EE) return;
    int pos = atomicAdd(&cur[col[e]], 1);
    srow[pos] = row[e];
}

// ---------------- fused projection weight ----------------
__global__ __launch_bounds__(256)
void wp_kernel(const float* __restrict__ out_w, const float* __restrict__ out_b,
               const float* __restrict__ proj_w, const float* __restrict__ proj_b,
               float* __restrict__ Wp, float* __restrict__ bp) {
    int gid = blockIdx.x * 256 + threadIdx.x;   // 8192 threads
    int i = gid >> 6;
    int c = gid & 63;
    float acc = 0.0f;
    #pragma unroll 8
    for (int o = 0; o < FF; o++)
        acc += out_w[o * FF + i] * proj_w[o * CC + c];
    Wp[i * CC + c] = acc;
    if (i == 0) {
        float b = proj_b[c];
        #pragma unroll 8
        for (int o = 0; o < FF; o++)
            b += out_b[o] * proj_w[o * CC + c];
        bp[c] = b;
    }
}

// ---------------- segmented gather (8-deep unroll) ----------------
__global__ __launch_bounds__(256)
void gather_kernel(const float* __restrict__ H,
                   const int* __restrict__ srow, const int* __restrict__ off,
                   const float* __restrict__ dinv, const float* __restrict__ bias,
                   float* __restrict__ out) {
    int warp = threadIdx.x >> 5;
    int lane = threadIdx.x & 31;
    int c = blockIdx.x * 8 + warp;
    int d = lane * 4;

    float dc = dinv[c];
    float4 hs = *(const float4*)(H + c * HID + d);
    float4 acc = make_float4(dc * hs.x, dc * hs.y, dc * hs.z, dc * hs.w);

    int i = off[c];
    int e_ = off[c + 1];
    for (; i + 8 <= e_; i += 8) {
        int   r[8];
        float w[8];
        float4 h[8];
        #pragma unroll
        for (int u = 0; u < 8; u++) r[u] = srow[i + u];
        #pragma unroll
        for (int u = 0; u < 8; u++) w[u] = dinv[r[u]];
        #pragma unroll
        for (int u = 0; u < 8; u++) h[u] = *(const float4*)(H + r[u] * HID + d);
        #pragma unroll
        for (int u = 0; u < 8; u++) {
            acc.x += w[u] * h[u].x;
            acc.y += w[u] * h[u].y;
            acc.z += w[u] * h[u].z;
            acc.w += w[u] * h[u].w;
        }
    }
    for (; i < e_; i++) {
        int r = srow[i];
        float w = dinv[r];
        float4 h = *(const float4*)(H + r * HID + d);
        acc.x += w * h.x; acc.y += w * h.y; acc.z += w * h.z; acc.w += w * h.w;
    }

    float4 b = *(const float4*)(bias + d);
    float4 v;
    v.x = fmaxf(b.x + dc * acc.x, 0.0f);
    v.y = fmaxf(b.y + dc * acc.y, 0.0f);
    v.z = fmaxf(b.z + dc * acc.z, 0.0f);
    v.w = fmaxf(b.w + dc * acc.w, 0.0f);
    *(float4*)(out + c * HID + d) = v;
}

// ---------------- software-pipelined SGEMM ----------------
template <int BM, int BN, bool TRANSB, bool HAS_BIAS, bool DO_ADD, bool DO_RELU>
__global__ __launch_bounds__(256)
void pgemm_kernel(const float* __restrict__ A, const float* __restrict__ B,
                  const float* __restrict__ bias, const float* __restrict__ add,
                  float* __restrict__ C, int M, int N, int K) {
    constexpr int NA = BM / 32;
    constexpr int NB = BN / 32;
    constexpr int RM = BM / 16;
    constexpr int RN = BN / 16;
    __shared__ float As[2][32][BM + 4];
    __shared__ float Bs[2][32][BN];

    const int tid = threadIdx.x;
    const int tx = tid & 15, ty = tid >> 4;
    const int m0 = blockIdx.y * BM, n0 = blockIdx.x * BN;

    float4 pa[NA], pb[NB];

    auto loadA = [&](int k0) {
        #pragma unroll
        for (int i = 0; i < NA; i++) {
            int fl = tid + i * 256;
            int ar = fl >> 3, ac = (fl & 7) * 4;
            pa[i] = *(const float4*)(A + (m0 + ar) * K + k0 + ac);
        }
    };
    auto storeA = [&](int buf) {
        #pragma unroll
        for (int i = 0; i < NA; i++) {
            int fl = tid + i * 256;
            int ar = fl >> 3, ac = (fl & 7) * 4;
            As[buf][ac + 0][ar] = pa[i].x;
            As[buf][ac + 1][ar] = pa[i].y;
            As[buf][ac + 2][ar] = pa[i].z;
            As[buf][ac + 3][ar] = pa[i].w;
        }
    };
    auto loadB = [&](int k0) {
        #pragma unroll
        for (int i = 0; i < NB; i++) {
            int fl = tid + i * 256;
            if (!TRANSB) {
                int br = fl / (BN / 4), bc = (fl % (BN / 4)) * 4;
                pb[i] = *(const float4*)(B + (k0 + br) * N + n0 + bc);
            } else {
                int bn = fl >> 3, bk = (fl & 7) * 4;
                pb[i] = *(const float4*)(B + (n0 + bn) * K + k0 + bk);
            }
        }
    };
    auto storeB = [&](int buf) {
        #pragma unroll
        for (int i = 0; i < NB; i++) {
            int fl = tid + i * 256;
            if (!TRANSB) {
                int br = fl / (BN / 4), bc = (fl % (BN / 4)) * 4;
                *(float4*)&Bs[buf][br][bc] = pb[i];
            } else {
                int bn = fl >> 3, bk = (fl & 7) * 4;
                Bs[buf][bk + 0][bn] = pb[i].x;
                Bs[buf][bk + 1][bn] = pb[i].y;
                Bs[buf][bk + 2][bn] = pb[i].z;
                Bs[buf][bk + 3][bn] = pb[i].w;
            }
        }
    };

    loadA(0); loadB(0);
    storeA(0); storeB(0);
    __syncthreads();

    float acc[RM][RN];
    #pragma unroll
    for (int i = 0; i < RM; i++)
        #pragma unroll
        for (int j = 0; j < RN; j++) acc[i][j] = 0.0f;

    const int nit = K >> 5;
    for (int it = 0; it < nit; it++) {
        const int cur = it & 1;
        if (it + 1 < nit) { loadA((it + 1) * 32); loadB((it + 1) * 32); }

        #pragma unroll
        for (int kk = 0; kk < 32; kk++) {
            float a[RM], b[RN];
            if (RM == 4) {
                float4 av = *(const float4*)&As[cur][kk][ty * 4];
                a[0] = av.x; a[1] = av.y; a[2] = av.z; a[3] = av.w;
            } else {
                float2 av = *(const float2*)&As[cur][kk][ty * 2];
                a[0] = av.x; a[1] = av.y;
            }
            if (RN == 4) {
                float4 bv = *(const float4*)&Bs[cur][kk][tx * 4];
                b[0] = bv.x; b[1] = bv.y; b[2] = bv.z; b[3] = bv.w;
            } else {
                float2 bv = *(const float2*)&Bs[cur][kk][tx * 2];
                b[0] = bv.x; b[1] = bv.y;
            }
            #pragma unroll
            for (int i = 0; i < RM; i++)
                #pragma unroll
                for (int j = 0; j < RN; j++)
                    acc[i][j] += a[i] * b[j];
        }

        if (it + 1 < nit) {
            storeA((it + 1) & 1); storeB((it + 1) & 1);
            __syncthreads();
        }
    }

    #pragma unroll
    for (int i = 0; i < RM; i++) {
        int r = m0 + ty * RM + i;
        #pragma unroll
        for (int j = 0; j < RN; j++) {
            int c = n0 + tx * RN + j;
            float v = acc[i][j];
            if (HAS_BIAS) v += bias[c];
            if (DO_ADD)  v += add[r * N + c];
            if (DO_RELU) v = fmaxf(v, 0.0f);
            C[r * N + c] = v;
        }
    }
}

// ---------------- fp16 tensor-core flash attention (round-14) ----------------
__global__ __launch_bounds__(256)
void attn_f16_kernel(const float* __restrict__ QKV, float* __restrict__ O) {
    const int h    = blockIdx.y;
    const int warp = threadIdx.x >> 5;
    const int lane = threadIdx.x & 31;
    const int g    = lane >> 2;
    const int t    = lane & 3;
    const int q0   = blockIdx.x * 128 + warp * 16;

    __shared__ unsigned Kw[64 * 12];   // f16x2 K: [key][dim pair], 3 KB
    __shared__ __half   Vt[16][72];    // fp16 V^T: [dim][key], 2.25 KB

    const float qscale = 0.25f * 1.4426950408889634f;

    unsigned qa0, qa1, qa2, qa3;
    {
        const float* r0 = QKV + (q0 + g)     * 384 + h * HDIM;
        const float* r1 = QKV + (q0 + g + 8) * 384 + h * HDIM;
        qa0 = f16x2_hl(r0[2 * t + 1] * qscale, r0[2 * t]     * qscale);
        qa1 = f16x2_hl(r1[2 * t + 1] * qscale, r1[2 * t]     * qscale);
        qa2 = f16x2_hl(r0[2 * t + 9] * qscale, r0[2 * t + 8] * qscale);
        qa3 = f16x2_hl(r1[2 * t + 9] * qscale, r1[2 * t + 8] * qscale);
    }

    float o[2][4];
    #pragma unroll
    for (int dt = 0; dt < 2; dt++)
        #pragma unroll
        for (int i = 0; i < 4; i++) o[dt][i] = 0.0f;
    float l0 = 0.0f, l1 = 0.0f;

    const unsigned* Vtw = (const unsigned*)&Vt[0][0];

    for (int k0 = 0; k0 < NN; k0 += 64) {
        __syncthreads();
        {
            int key = threadIdx.x & 63;
            int dh  = (threadIdx.x >> 6) * 4;
            const float* kb = QKV + (k0 + key) * 384 + FF + h * HDIM + dh;
            float4 kv = *(const float4*)kb;
            float4 vv = *(const float4*)(kb + FF);
            Kw[key * 12 + (dh >> 1) + 0] = f16x2_hl(kv.y, kv.x);
            Kw[key * 12 + (dh >> 1) + 1] = f16x2_hl(kv.w, kv.z);
            Vt[dh + 0][key] = __float2half_rn(vv.x);
            Vt[dh + 1][key] = __float2half_rn(vv.y);
            Vt[dh + 2][key] = __float2half_rn(vv.z);
            Vt[dh + 3][key] = __float2half_rn(vv.w);
        }
        __syncthreads();

        float c[8][4];
        #pragma unroll
        for (int j = 0; j < 8; j++) {
            c[j][0] = c[j][1] = c[j][2] = c[j][3] = 0.0f;
            unsigned b0 = Kw[(j * 8 + g) * 12 + t];
            unsigned b1 = Kw[(j * 8 + g) * 12 + t + 4];
            mma_f16(c[j], qa0, qa1, qa2, qa3, b0, b1);
        }

        #pragma unroll
        for (int j = 0; j < 8; j++) {
            c[j][0] = ex2(c[j][0] - 8.0f);
            c[j][1] = ex2(c[j][1] - 8.0f);
            c[j][2] = ex2(c[j][2] - 8.0f);
            c[j][3] = ex2(c[j][3] - 8.0f);
            l0 += c[j][0] + c[j][1];
            l1 += c[j][2] + c[j][3];
        }

        #pragma unroll
        for (int kt = 0; kt < 4; kt++) {
            unsigned a0 = f16x2_hl(c[2 * kt][1],     c[2 * kt][0]);
            unsigned a1 = f16x2_hl(c[2 * kt][3],     c[2 * kt][2]);
            unsigned a2 = f16x2_hl(c[2 * kt + 1][1], c[2 * kt + 1][0]);
            unsigned a3 = f16x2_hl(c[2 * kt + 1][3], c[2 * kt + 1][2]);
            #pragma unroll
            for (int dt = 0; dt < 2; dt++) {
                int d = dt * 8 + g;
                unsigned b0 = Vtw[d * 36 + kt * 8 + t];
                unsigned b1 = Vtw[d * 36 + kt * 8 + t + 4];
                mma_f16(o[dt], a0, a1, a2, a3, b0, b1);
            }
        }
    }

    l0 += __shfl_xor_sync(0xffffffffu, l0, 1);
    l0 += __shfl_xor_sync(0xffffffffu, l0, 2);
    l1 += __shfl_xor_sync(0xffffffffu, l1, 1);
    l1 += __shfl_xor_sync(0xffffffffu, l1, 2);
    float inv0 = 1.0f / l0;
    float inv1 = 1.0f / l1;

    #pragma unroll
    for (int dt = 0; dt < 2; dt++) {
        int col = h * HDIM + dt * 8 + 2 * t;
        float2 v0 = make_float2(o[dt][0] * inv0, o[dt][1] * inv0);
        float2 v1 = make_float2(o[dt][2] * inv1, o[dt][3] * inv1);
        *(float2*)(O + (q0 + g)     * FF + col) = v0;
        *(float2*)(O + (q0 + g + 8) * FF + col) = v1;
    }
}

// ---------------- launch ----------------
extern "C" void kernel_launch(void* const* d_in, const int* in_sizes, int n_in,
                              void* d_out, int out_size) {
    const float* x          = (const float*)d_in[0];
    const int*   edge_index = (const int*)  d_in[1];
    const float* W1         = (const float*)d_in[2];
    const float* b1         = (const float*)d_in[3];
    const float* W2         = (const float*)d_in[4];
    const float* b2         = (const float*)d_in[5];
    const float* W3         = (const float*)d_in[6];
    const float* b3         = (const float*)d_in[7];
    const float* in_w       = (const float*)d_in[8];
    const float* in_b       = (const float*)d_in[9];
    const float* out_w      = (const float*)d_in[10];
    const float* out_b      = (const float*)d_in[11];
    const float* proj_w     = (const float*)d_in[12];
    const float* proj_b     = (const float*)d_in[13];
    float* out = (float*)d_out;

    const int* row = edge_index;
    const int* col = edge_index + EE;

    float *H, *G, *G2, *QKV, *O, *GNN, *Wp, *bp, *dinv;
    int *cnt, *off, *cur, *srow;
    cudaGetSymbolAddress((void**)&H,    g_H);
    cudaGetSymbolAddress((void**)&G,    g_G);
    cudaGetSymbolAddress((void**)&G2,   g_G2);
    cudaGetSymbolAddress((void**)&QKV,  g_QKV);
    cudaGetSymbolAddress((void**)&O,    g_O);
    cudaGetSymbolAddress((void**)&GNN,  g_GNN);
    cudaGetSymbolAddress((void**)&Wp,   g_Wp);
    cudaGetSymbolAddress((void**)&bp,   g_bp);
    cudaGetSymbolAddress((void**)&dinv, g_dinv);
    cudaGetSymbolAddress((void**)&cnt,  g_count);
    cudaGetSymbolAddress((void**)&off,  g_off);
    cudaGetSymbolAddress((void**)&cur,  g_cur);
    cudaGetSymbolAddress((void**)&srow, g_srow);

    // Fork: transformer branch on the per-thread stream, GNN branch on the
    // capture (legacy) stream; join before the final fused GEMM.
    cudaStream_t tf = cudaStreamPerThread;
    cudaEvent_t evFork, evJoin;
    cudaEventCreateWithFlags(&evFork, cudaEventDisableTiming);
    cudaEventCreateWithFlags(&evJoin, cudaEventDisableTiming);

    cudaEventRecord(evFork, 0);
    cudaStreamWaitEvent(tf, evFork, 0);

    // ---- Transformer branch (tf stream): QKV -> attention -> Wp ----
    pgemm_kernel<64, 64, true, true, false, false>
        <<<dim3(3 * FF / 64, NN / 64), 256, 0, tf>>>(x, in_w, in_b, nullptr, QKV, NN, 3 * FF, FF);
    attn_f16_kernel<<<dim3(NN / 128, HEADS), 256, 0, tf>>>(QKV, O);
    wp_kernel<<<FF * CC / 256, 256, 0, tf>>>(out_w, out_b, proj_w, proj_b, Wp, bp);
    cudaEventRecord(evJoin, tf);

    // ---- GNN branch (legacy stream) ----
    // CSR build (g_count is all-zero on entry; scan restores it)
    hist_kernel<<<(EE / 4 + 255) / 256, 256>>>(col, cnt);
    scan_kernel<<<1, 1024>>>(cnt, off, cur, dinv);
    reorder_kernel<<<(EE + 255) / 256, 256>>>(row, col, cur, srow);

    pgemm_kernel<64, 32, false, false, false, false>
        <<<dim3(HID / 32, NN / 64), 256>>>(x, W1, nullptr, nullptr, H, NN, HID, FF);
    gather_kernel<<<NN / 8, 256>>>(H, srow, off, dinv, b1, G);

    pgemm_kernel<64, 32, false, false, false, false>
        <<<dim3(HID / 32, NN / 64), 256>>>(G, W2, nullptr, nullptr, H, NN, HID, HID);
    gather_kernel<<<NN / 8, 256>>>(H, srow, off, dinv, b2, G2);

    pgemm_kernel<32, 32, false, true, false, false>
        <<<dim3(CC / 32, NN / 32), 256>>>(G2, W3, b3, nullptr, GNN, NN, CC, HID);

    // ---- join: out = relu(O @ Wp + bp + GNN) ----
    cudaStreamWaitEvent(0, evJoin, 0);
    pgemm_kernel<32, 32, false, true, true, true>
        <<<dim3(CC / 32, NN / 32), 256>>>(O, Wp, bp, GNN, out, NN, CC, FF);
}

// round 16
// speedup vs baseline: 1.4906x; 1.4906x over previous
#include <cuda_runtime.h>
#include <cuda_fp16.h>
#include <cstdint>

// Problem constants
#define NN 4096
#define FF 128
#define HID 128
#define HEADS 8
#define HDIM 16
#define CC 64
#define EE 131072

// ---------------- scratch (no allocation allowed) ----------------
__device__ float g_H[NN * HID];     // GEMM output of X@W (pre-gather)
__device__ float g_G[NN * HID];     // conv1 output (post-relu)
__device__ float g_G2[NN * HID];    // conv2 output (post-relu)
__device__ float g_QKV[NN * 3 * FF];
__device__ float g_O[NN * FF];      // attention output
__device__ float g_GNN[NN * CC];    // gnn branch output
__device__ float g_Wp[FF * CC];     // fused out_proj*proj weight
__device__ float g_bp[CC];          // fused bias
__device__ float g_dinv[NN];
__device__ int   g_count[NN];       // invariant: all-zero at kernel-launch entry
__device__ int   g_off[NN + 1];
__device__ int   g_cur[NN];
__device__ int   g_srow[EE];

// ---------------- helpers ----------------
__device__ __forceinline__ unsigned f16x2_hl(float hi, float lo) {
    unsigned u; asm("cvt.rn.f16x2.f32 %0, %1, %2;" : "=r"(u) : "f"(hi), "f"(lo)); return u;
}
__device__ __forceinline__ float ex2(float x) {
    float y; asm("ex2.approx.ftz.f32 %0, %1;" : "=f"(y) : "f"(x)); return y;
}
__device__ __forceinline__ void mma_f16(float c[4], unsigned a0, unsigned a1,
                                        unsigned a2, unsigned a3,
                                        unsigned b0, unsigned b1) {
    asm("mma.sync.aligned.m16n8k16.row.col.f32.f16.f16.f32 "
        "{%0,%1,%2,%3}, {%4,%5,%6,%7}, {%8,%9}, {%0,%1,%2,%3};"
        : "+f"(c[0]), "+f"(c[1]), "+f"(c[2]), "+f"(c[3])
        : "r"(a0), "r"(a1), "r"(a2), "r"(a3), "r"(b0), "r"(b1));
}

// ---------------- CSR build kernels ----------------
// hist: 4 edges per thread via int4 (g_count must be all-zero on entry;
// scan_kernel restores that invariant each launch)
__global__ void hist_kernel(const int* __restrict__ col, int* __restrict__ count) {
    int i = blockIdx.x * blockDim.x + threadIdx.x;
    if (i >= EE / 4) return;
    int4 v = ((const int4*)col)[i];
    atomicAdd(&count[v.x], 1);
    atomicAdd(&count[v.y], 1);
    atomicAdd(&count[v.z], 1);
    atomicAdd(&count[v.w], 1);
}

__global__ __launch_bounds__(1024)
void scan_kernel(int* __restrict__ count, int* __restrict__ off,
                 int* __restrict__ cur, float* __restrict__ dinv) {
    __shared__ int wsum[32];
    int t = threadIdx.x;
    int lane = t & 31, warp = t >> 5;
    int base = t * 4;
    int v0 = count[base + 0], v1 = count[base + 1];
    int v2 = count[base + 2], v3 = count[base + 3];
    // restore the all-zero invariant for the next launch
    count[base + 0] = 0; count[base + 1] = 0;
    count[base + 2] = 0; count[base + 3] = 0;
    dinv[base + 0] = rsqrtf(1.0f + (float)v0);
    dinv[base + 1] = rsqrtf(1.0f + (float)v1);
    dinv[base + 2] = rsqrtf(1.0f + (float)v2);
    dinv[base + 3] = rsqrtf(1.0f + (float)v3);
    int s = v0 + v1 + v2 + v3;
    int x = s;
    #pragma unroll
    for (int d = 1; d < 32; d <<= 1) {
        int y = __shfl_up_sync(0xffffffffu, x, d);
        if (lane >= d) x += y;
    }
    if (lane == 31) wsum[warp] = x;
    __syncthreads();
    if (warp == 0) {
        int w = wsum[lane];
        #pragma unroll
        for (int d = 1; d < 32; d <<= 1) {
            int y = __shfl_up_sync(0xffffffffu, w, d);
            if (lane >= d) w += y;
        }
        wsum[lane] = w;
    }
    __syncthreads();
    int run = x - s + (warp ? wsum[warp - 1] : 0);
    off[base + 0] = run; cur[base + 0] = run; run += v0;
    off[base + 1] = run; cur[base + 1] = run; run += v1;
    off[base + 2] = run; cur[base + 2] = run; run += v2;
    off[base + 3] = run; cur[base + 3] = run; run += v3;
    if (t == 1023) off[NN] = run;
}

__global__ void reorder_kernel(const int* __restrict__ row, const int* __restrict__ col,
                               int* __restrict__ cur, int* __restrict__ srow) {
    int e = blockIdx.x * blockDim.x + threadIdx.x;
    if (e >= EE) return;
    int pos = atomicAdd(&cur[col[e]], 1);
    srow[pos] = row[e];
}

// ---------------- fused projection weight ----------------
__global__ __launch_bounds__(256)
void wp_kernel(const float* __restrict__ out_w, const float* __restrict__ out_b,
               const float* __restrict__ proj_w, const float* __restrict__ proj_b,
               float* __restrict__ Wp, float* __restrict__ bp) {
    int gid = blockIdx.x * 256 + threadIdx.x;   // 8192 threads
    int i = gid >> 6;
    int c = gid & 63;
    float acc = 0.0f;
    #pragma unroll 8
    for (int o = 0; o < FF; o++)
        acc += out_w[o * FF + i] * proj_w[o * CC + c];
    Wp[i * CC + c] = acc;
    if (i == 0) {
        float b = proj_b[c];
        #pragma unroll 8
        for (int o = 0; o < FF; o++)
            b += out_b[o] * proj_w[o * CC + c];
        bp[c] = b;
    }
}

// ---------------- segmented gather (8-deep unroll) ----------------
__global__ __launch_bounds__(256)
void gather_kernel(const float* __restrict__ H,
                   const int* __restrict__ srow, const int* __restrict__ off,
                   const float* __restrict__ dinv, const float* __restrict__ bias,
                   float* __restrict__ out) {
    int warp = threadIdx.x >> 5;
    int lane = threadIdx.x & 31;
    int c = blockIdx.x * 8 + warp;
    int d = lane * 4;

    float dc = dinv[c];
    float4 hs = *(const float4*)(H + c * HID + d);
    float4 acc = make_float4(dc * hs.x, dc * hs.y, dc * hs.z, dc * hs.w);

    int i = off[c];
    int e_ = off[c + 1];
    for (; i + 8 <= e_; i += 8) {
        int   r[8];
        float w[8];
        float4 h[8];
        #pragma unroll
        for (int u = 0; u < 8; u++) r[u] = srow[i + u];
        #pragma unroll
        for (int u = 0; u < 8; u++) w[u] = dinv[r[u]];
        #pragma unroll
        for (int u = 0; u < 8; u++) h[u] = *(const float4*)(H + r[u] * HID + d);
        #pragma unroll
        for (int u = 0; u < 8; u++) {
            acc.x += w[u] * h[u].x;
            acc.y += w[u] * h[u].y;
            acc.z += w[u] * h[u].z;
            acc.w += w[u] * h[u].w;
        }
    }
    for (; i < e_; i++) {
        int r = srow[i];
        float w = dinv[r];
        float4 h = *(const float4*)(H + r * HID + d);
        acc.x += w * h.x; acc.y += w * h.y; acc.z += w * h.z; acc.w += w * h.w;
    }

    float4 b = *(const float4*)(bias + d);
    float4 v;
    v.x = fmaxf(b.x + dc * acc.x, 0.0f);
    v.y = fmaxf(b.y + dc * acc.y, 0.0f);
    v.z = fmaxf(b.z + dc * acc.z, 0.0f);
    v.w = fmaxf(b.w + dc * acc.w, 0.0f);
    *(float4*)(out + c * HID + d) = v;
}

// ---------------- software-pipelined SGEMM ----------------
template <int BM, int BN, bool TRANSB, bool HAS_BIAS, bool DO_ADD, bool DO_RELU>
__global__ __launch_bounds__(256)
void pgemm_kernel(const float* __restrict__ A, const float* __restrict__ B,
                  const float* __restrict__ bias, const float* __restrict__ add,
                  float* __restrict__ C, int M, int N, int K) {
    constexpr int NA = BM / 32;
    constexpr int NB = BN / 32;
    constexpr int RM = BM / 16;
    constexpr int RN = BN / 16;
    __shared__ float As[2][32][BM + 4];
    __shared__ float Bs[2][32][BN];

    const int tid = threadIdx.x;
    const int tx = tid & 15, ty = tid >> 4;
    const int m0 = blockIdx.y * BM, n0 = blockIdx.x * BN;

    float4 pa[NA], pb[NB];

    auto loadA = [&](int k0) {
        #pragma unroll
        for (int i = 0; i < NA; i++) {
            int fl = tid + i * 256;
            int ar = fl >> 3, ac = (fl & 7) * 4;
            pa[i] = *(const float4*)(A + (m0 + ar) * K + k0 + ac);
        }
    };
    auto storeA = [&](int buf) {
        #pragma unroll
        for (int i = 0; i < NA; i++) {
            int fl = tid + i * 256;
            int ar = fl >> 3, ac = (fl & 7) * 4;
            As[buf][ac + 0][ar] = pa[i].x;
            As[buf][ac + 1][ar] = pa[i].y;
            As[buf][ac + 2][ar] = pa[i].z;
            As[buf][ac + 3][ar] = pa[i].w;
        }
    };
    auto loadB = [&](int k0) {
        #pragma unroll
        for (int i = 0; i < NB; i++) {
            int fl = tid + i * 256;
            if (!TRANSB) {
                int br = fl / (BN / 4), bc = (fl % (BN / 4)) * 4;
                pb[i] = *(const float4*)(B + (k0 + br) * N + n0 + bc);
            } else {
                int bn = fl >> 3, bk = (fl & 7) * 4;
                pb[i] = *(const float4*)(B + (n0 + bn) * K + k0 + bk);
            }
        }
    };
    auto storeB = [&](int buf) {
        #pragma unroll
        for (int i = 0; i < NB; i++) {
            int fl = tid + i * 256;
            if (!TRANSB) {
                int br = fl / (BN / 4), bc = (fl % (BN / 4)) * 4;
                *(float4*)&Bs[buf][br][bc] = pb[i];
            } else {
                int bn = fl >> 3, bk = (fl & 7) * 4;
                Bs[buf][bk + 0][bn] = pb[i].x;
                Bs[buf][bk + 1][bn] = pb[i].y;
                Bs[buf][bk + 2][bn] = pb[i].z;
                Bs[buf][bk + 3][bn] = pb[i].w;
            }
        }
    };

    loadA(0); loadB(0);
    storeA(0); storeB(0);
    __syncthreads();

    float acc[RM][RN];
    #pragma unroll
    for (int i = 0; i < RM; i++)
        #pragma unroll
        for (int j = 0; j < RN; j++) acc[i][j] = 0.0f;

    const int nit = K >> 5;
    for (int it = 0; it < nit; it++) {
        const int cur = it & 1;
        if (it + 1 < nit) { loadA((it + 1) * 32); loadB((it + 1) * 32); }

        #pragma unroll
        for (int kk = 0; kk < 32; kk++) {
            float a[RM], b[RN];
            if (RM == 4) {
                float4 av = *(const float4*)&As[cur][kk][ty * 4];
                a[0] = av.x; a[1] = av.y; a[2] = av.z; a[3] = av.w;
            } else {
                float2 av = *(const float2*)&As[cur][kk][ty * 2];
                a[0] = av.x; a[1] = av.y;
            }
            if (RN == 4) {
                float4 bv = *(const float4*)&Bs[cur][kk][tx * 4];
                b[0] = bv.x; b[1] = bv.y; b[2] = bv.z; b[3] = bv.w;
            } else {
                float2 bv = *(const float2*)&Bs[cur][kk][tx * 2];
                b[0] = bv.x; b[1] = bv.y;
            }
            #pragma unroll
            for (int i = 0; i < RM; i++)
                #pragma unroll
                for (int j = 0; j < RN; j++)
                    acc[i][j] += a[i] * b[j];
        }

        if (it + 1 < nit) {
            storeA((it + 1) & 1); storeB((it + 1) & 1);
            __syncthreads();
        }
    }

    #pragma unroll
    for (int i = 0; i < RM; i++) {
        int r = m0 + ty * RM + i;
        #pragma unroll
        for (int j = 0; j < RN; j++) {
            int c = n0 + tx * RN + j;
            float v = acc[i][j];
            if (HAS_BIAS) v += bias[c];
            if (DO_ADD)  v += add[r * N + c];
            if (DO_RELU) v = fmaxf(v, 0.0f);
            C[r * N + c] = v;
        }
    }
}

// ---------------- fp16 tensor-core flash attention (round-14) ----------------
__global__ __launch_bounds__(256)
void attn_f16_kernel(const float* __restrict__ QKV, float* __restrict__ O) {
    const int h    = blockIdx.y;
    const int warp = threadIdx.x >> 5;
    const int lane = threadIdx.x & 31;
    const int g    = lane >> 2;
    const int t    = lane & 3;
    const int q0   = blockIdx.x * 128 + warp * 16;

    __shared__ unsigned Kw[64 * 12];   // f16x2 K: [key][dim pair], 3 KB
    __shared__ __half   Vt[16][72];    // fp16 V^T: [dim][key], 2.25 KB

    const float qscale = 0.25f * 1.4426950408889634f;

    unsigned qa0, qa1, qa2, qa3;
    {
        const float* r0 = QKV + (q0 + g)     * 384 + h * HDIM;
        const float* r1 = QKV + (q0 + g + 8) * 384 + h * HDIM;
        qa0 = f16x2_hl(r0[2 * t + 1] * qscale, r0[2 * t]     * qscale);
        qa1 = f16x2_hl(r1[2 * t + 1] * qscale, r1[2 * t]     * qscale);
        qa2 = f16x2_hl(r0[2 * t + 9] * qscale, r0[2 * t + 8] * qscale);
        qa3 = f16x2_hl(r1[2 * t + 9] * qscale, r1[2 * t + 8] * qscale);
    }

    float o[2][4];
    #pragma unroll
    for (int dt = 0; dt < 2; dt++)
        #pragma unroll
        for (int i = 0; i < 4; i++) o[dt][i] = 0.0f;
    float l0 = 0.0f, l1 = 0.0f;

    const unsigned* Vtw = (const unsigned*)&Vt[0][0];

    for (int k0 = 0; k0 < NN; k0 += 64) {
        __syncthreads();
        {
            int key = threadIdx.x & 63;
            int dh  = (threadIdx.x >> 6) * 4;
            const float* kb = QKV + (k0 + key) * 384 + FF + h * HDIM + dh;
            float4 kv = *(const float4*)kb;
            float4 vv = *(const float4*)(kb + FF);
            Kw[key * 12 + (dh >> 1) + 0] = f16x2_hl(kv.y, kv.x);
            Kw[key * 12 + (dh >> 1) + 1] = f16x2_hl(kv.w, kv.z);
            Vt[dh + 0][key] = __float2half_rn(vv.x);
            Vt[dh + 1][key] = __float2half_rn(vv.y);
            Vt[dh + 2][key] = __float2half_rn(vv.z);
            Vt[dh + 3][key] = __float2half_rn(vv.w);
        }
        __syncthreads();

        float c[8][4];
        #pragma unroll
        for (int j = 0; j < 8; j++) {
            c[j][0] = c[j][1] = c[j][2] = c[j][3] = 0.0f;
            unsigned b0 = Kw[(j * 8 + g) * 12 + t];
            unsigned b1 = Kw[(j * 8 + g) * 12 + t + 4];
            mma_f16(c[j], qa0, qa1, qa2, qa3, b0, b1);
        }

        #pragma unroll
        for (int j = 0; j < 8; j++) {
            c[j][0] = ex2(c[j][0] - 8.0f);
            c[j][1] = ex2(c[j][1] - 8.0f);
            c[j][2] = ex2(c[j][2] - 8.0f);
            c[j][3] = ex2(c[j][3] - 8.0f);
            l0 += c[j][0] + c[j][1];
            l1 += c[j][2] + c[j][3];
        }

        #pragma unroll
        for (int kt = 0; kt < 4; kt++) {
            unsigned a0 = f16x2_hl(c[2 * kt][1],     c[2 * kt][0]);
            unsigned a1 = f16x2_hl(c[2 * kt][3],     c[2 * kt][2]);
            unsigned a2 = f16x2_hl(c[2 * kt + 1][1], c[2 * kt + 1][0]);
            unsigned a3 = f16x2_hl(c[2 * kt + 1][3], c[2 * kt + 1][2]);
            #pragma unroll
            for (int dt = 0; dt < 2; dt++) {
                int d = dt * 8 + g;
                unsigned b0 = Vtw[d * 36 + kt * 8 + t];
                unsigned b1 = Vtw[d * 36 + kt * 8 + t + 4];
                mma_f16(o[dt], a0, a1, a2, a3, b0, b1);
            }
        }
    }

    l0 += __shfl_xor_sync(0xffffffffu, l0, 1);
    l0 += __shfl_xor_sync(0xffffffffu, l0, 2);
    l1 += __shfl_xor_sync(0xffffffffu, l1, 1);
    l1 += __shfl_xor_sync(0xffffffffu, l1, 2);
    float inv0 = 1.0f / l0;
    float inv1 = 1.0f / l1;

    #pragma unroll
    for (int dt = 0; dt < 2; dt++) {
        int col = h * HDIM + dt * 8 + 2 * t;
        float2 v0 = make_float2(o[dt][0] * inv0, o[dt][1] * inv0);
        float2 v1 = make_float2(o[dt][2] * inv1, o[dt][3] * inv1);
        *(float2*)(O + (q0 + g)     * FF + col) = v0;
        *(float2*)(O + (q0 + g + 8) * FF + col) = v1;
    }
}

// ---------------- launch (single stream, round-14 order) ----------------
extern "C" void kernel_launch(void* const* d_in, const int* in_sizes, int n_in,
                              void* d_out, int out_size) {
    const float* x          = (const float*)d_in[0];
    const int*   edge_index = (const int*)  d_in[1];
    const float* W1         = (const float*)d_in[2];
    const float* b1         = (const float*)d_in[3];
    const float* W2         = (const float*)d_in[4];
    const float* b2         = (const float*)d_in[5];
    const float* W3         = (const float*)d_in[6];
    const float* b3         = (const float*)d_in[7];
    const float* in_w       = (const float*)d_in[8];
    const float* in_b       = (const float*)d_in[9];
    const float* out_w      = (const float*)d_in[10];
    const float* out_b      = (const float*)d_in[11];
    const float* proj_w     = (const float*)d_in[12];
    const float* proj_b     = (const float*)d_in[13];
    float* out = (float*)d_out;

    const int* row = edge_index;
    const int* col = edge_index + EE;

    float *H, *G, *G2, *QKV, *O, *GNN, *Wp, *bp, *dinv;
    int *cnt, *off, *cur, *srow;
    cudaGetSymbolAddress((void**)&H,    g_H);
    cudaGetSymbolAddress((void**)&G,    g_G);
    cudaGetSymbolAddress((void**)&G2,   g_G2);
    cudaGetSymbolAddress((void**)&QKV,  g_QKV);
    cudaGetSymbolAddress((void**)&O,    g_O);
    cudaGetSymbolAddress((void**)&GNN,  g_GNN);
    cudaGetSymbolAddress((void**)&Wp,   g_Wp);
    cudaGetSymbolAddress((void**)&bp,   g_bp);
    cudaGetSymbolAddress((void**)&dinv, g_dinv);
    cudaGetSymbolAddress((void**)&cnt,  g_count);
    cudaGetSymbolAddress((void**)&off,  g_off);
    cudaGetSymbolAddress((void**)&cur,  g_cur);
    cudaGetSymbolAddress((void**)&srow, g_srow);

    // ---- independent precompute first (fills pipeline start) ----
    wp_kernel<<<FF * CC / 256, 256>>>(out_w, out_b, proj_w, proj_b, Wp, bp);

    // ---- CSR build (g_count all-zero on entry; scan restores it) ----
    hist_kernel<<<(EE / 4 + 255) / 256, 256>>>(col, cnt);
    scan_kernel<<<1, 1024>>>(cnt, off, cur, dinv);
    reorder_kernel<<<(EE + 255) / 256, 256>>>(row, col, cur, srow);

    // ---- GCN conv 1: H = x@W1 ; G = relu(gather) ----
    pgemm_kernel<64, 32, false, false, false, false>
        <<<dim3(HID / 32, NN / 64), 256>>>(x, W1, nullptr, nullptr, H, NN, HID, FF);
    gather_kernel<<<NN / 8, 256>>>(H, srow, off, dinv, b1, G);

    // ---- GCN conv 2: H = G@W2 ; G2 = relu(gather) ----
    pgemm_kernel<64, 32, false, false, false, false>
        <<<dim3(HID / 32, NN / 64), 256>>>(G, W2, nullptr, nullptr, H, NN, HID, HID);
    gather_kernel<<<NN / 8, 256>>>(H, srow, off, dinv, b2, G2);

    // ---- GNN head: GNN = G2 @ W3 + b3 ----
    pgemm_kernel<32, 32, false, true, false, false>
        <<<dim3(CC / 32, NN / 32), 256>>>(G2, W3, b3, nullptr, GNN, NN, CC, HID);

    // ---- Transformer branch ----
    pgemm_kernel<64, 64, true, true, false, false>
        <<<dim3(3 * FF / 64, NN / 64), 256>>>(x, in_w, in_b, nullptr, QKV, NN, 3 * FF, FF);
    attn_f16_kernel<<<dim3(NN / 128, HEADS), 256>>>(QKV, O);

    // ---- join: out = relu(O @ Wp + bp + GNN) ----
    pgemm_kernel<32, 32, false, true, true, true>
        <<<dim3(CC / 32, NN / 32), 256>>>(O, Wp, bp, GNN, out, NN, CC, FF);
}